// round 3
// baseline (speedup 1.0000x reference)
#include <cuda_runtime.h>
#include <cstdint>

// ============================================================================
// SIREN fused inference via mma.sync (HMMA bf16), .target sm_103-safe PTX.
//   x[1M,3] -> sin(30*(x@W0^T+b0)) -> 4x sin(h@Wi^T+bi) -> h@Wf^T+bf
// Activations resident in SMEM as bf16 hi/lo planes; weights pre-split into
// bf16 hi/lo chunks in a __device__ buffer, streamed L2->SMEM with cp.async.
// 3-MMA compensated product keeps rel_err ~1e-5 at bf16 tensor rate.
// ============================================================================

#define THREADS    256
#define M_TILE     128
#define N_POINTS   1048576
#define GRID_CTAS  (N_POINTS / M_TILE)      // 8192

// --- SMEM layout (bytes) ---
// A planes: [2][128 rows][264 halves] (16B row pad -> conflict-free ldmatrix)
#define A_LDB      528                      // bytes per row (264 halves)
#define A_PLANE    (128 * A_LDB)            // 67584
#define WBUF_OFF   (2 * A_PLANE)            // 135168
// W chunk: [256 n][40 halves] per plane (pad 8 halves), 2 planes, 2 buffers
#define W_LDB      80
#define W_PLANE    (256 * W_LDB)            // 20480
#define W_CHUNK    (2 * W_PLANE)            // 40960
#define P_OFF      (WBUF_OFF + 2 * W_CHUNK) // 217088
#define W0S_OFF    P_OFF
#define B0S_OFF    (W0S_OFF + 3072)
#define BIAS_OFF   (B0S_OFF + 1024)
#define WFS_OFF    (BIAS_OFF + 4096)
#define RED_OFF    (WFS_OFF + 1024)
#define SMEM_TOTAL (RED_OFF + 2048)         // 228352 <= 232448

// Packed split weights: 32 chunks (layer*8 + kc), each 40960B (hi plane, lo plane)
__device__ __align__(128) unsigned char g_wpacked[32 * W_CHUNK];

// ---------------------------------------------------------------------------
// helpers
// ---------------------------------------------------------------------------
__device__ __forceinline__ uint32_t smem_u32(const void* p) {
    uint32_t a;
    asm("{ .reg .u64 t; cvta.to.shared.u64 t, %1; cvt.u32.u64 %0, t; }"
        : "=r"(a) : "l"(p));
    return a;
}

#define CP_ASYNC16(dst, src) \
    asm volatile("cp.async.cg.shared.global [%0], [%1], 16;" :: "r"(dst), "l"(src) : "memory")
#define CP_COMMIT() asm volatile("cp.async.commit_group;" ::: "memory")
#define CP_WAIT(n)  asm volatile("cp.async.wait_group %0;" :: "n"(n) : "memory")

#define LDSM_X4(r0, r1, r2, r3, addr)                                          \
    asm volatile("ldmatrix.sync.aligned.m8n8.x4.shared.b16 {%0,%1,%2,%3}, [%4];" \
        : "=r"(r0), "=r"(r1), "=r"(r2), "=r"(r3) : "r"(addr))

#define MMA_BF16(d, a0, a1, a2, a3, b0, b1)                                    \
    asm volatile("mma.sync.aligned.m16n8k16.row.col.f32.bf16.bf16.f32 "        \
        "{%0,%1,%2,%3}, {%4,%5,%6,%7}, {%8,%9}, {%0,%1,%2,%3};"                \
        : "+f"((d)[0]), "+f"((d)[1]), "+f"((d)[2]), "+f"((d)[3])               \
        : "r"(a0), "r"(a1), "r"(a2), "r"(a3), "r"(b0), "r"(b1))

// exact truncation split of two fp32: hi word = [h0.hi16 | h1.hi16] (bf16x2),
// lo word = bf16x2 of exact residuals.
__device__ __forceinline__ void split_pack(float h0, float h1,
                                           uint32_t& hiw, uint32_t& low) {
    uint32_t u0 = __float_as_uint(h0), u1 = __float_as_uint(h1);
    hiw = __byte_perm(u0, u1, 0x7632);
    float l0 = h0 - __uint_as_float(u0 & 0xFFFF0000u);
    float l1 = h1 - __uint_as_float(u1 & 0xFFFF0000u);
    asm("cvt.rn.bf16x2.f32 %0, %1, %2;" : "=r"(low) : "f"(l1), "f"(l0));
}

// ---------------------------------------------------------------------------
// prep: W1..W4 fp32 [256,256] -> g_wpacked chunk planes
// chunk g = layer*8 + kc covers k in [kc*32, kc*32+32); row n: 32 data halves
// + 8 pad halves (pad never read by ldmatrix).
// ---------------------------------------------------------------------------
__global__ void prep_weights(const float* __restrict__ W1, const float* __restrict__ W2,
                             const float* __restrict__ W3, const float* __restrict__ W4) {
    int idx = blockIdx.x * blockDim.x + threadIdx.x;   // 131072 threads
    int w = idx & 15;              // word within chunk row (2 k-halves)
    int n = (idx >> 4) & 255;
    int g = idx >> 12;             // 0..31
    int layer = g >> 3, kc = g & 7;
    const float* W = (layer == 0) ? W1 : (layer == 1) ? W2 : (layer == 2) ? W3 : W4;
    int k0 = kc * 32 + w * 2;
    uint32_t hw, lw;
    split_pack(W[n * 256 + k0], W[n * 256 + k0 + 1], hw, lw);
    size_t base = (size_t)g * W_CHUNK + (size_t)n * W_LDB + (size_t)w * 4;
    *(uint32_t*)(g_wpacked + base)           = hw;
    *(uint32_t*)(g_wpacked + base + W_PLANE) = lw;
}

// ---------------------------------------------------------------------------
// main kernel
// ---------------------------------------------------------------------------
__device__ __forceinline__ void prefetch_chunk(uint32_t sb, int tid, int g) {
    const char* src = (const char*)g_wpacked + (size_t)g * W_CHUNK + (size_t)tid * 16;
    uint32_t dst = sb + WBUF_OFF + (uint32_t)(g & 1) * W_CHUNK + (uint32_t)tid * 16;
#pragma unroll
    for (int i = 0; i < 10; i++)
        CP_ASYNC16(dst + (uint32_t)i * 4096u, src + (size_t)i * 4096);
    CP_COMMIT();
}

__global__ void __launch_bounds__(THREADS, 1)
siren_mma_kernel(const float* __restrict__ xyt, const float* __restrict__ W0,
                 const float* __restrict__ b0, const float* __restrict__ b1,
                 const float* __restrict__ b2, const float* __restrict__ b3,
                 const float* __restrict__ b4, const float* __restrict__ Wf,
                 const float* __restrict__ bfp, float* __restrict__ out) {
    extern __shared__ char smem[];
    const uint32_t sb = smem_u32(smem);
    const int tid = threadIdx.x;
    const int lane = tid & 31;
    const int wid = tid >> 5;
    const int warp_m = wid & 1;    // 2 warps over M (64 rows each)
    const int warp_n = wid >> 1;   // 4 warps over N (64 cols each)

    // kick off weight streaming immediately
    prefetch_chunk(sb, tid, 0);
    prefetch_chunk(sb, tid, 1);

    // stage small params
    float* W0s  = (float*)(smem + W0S_OFF);
    float* b0s  = (float*)(smem + B0S_OFF);
    float* bias = (float*)(smem + BIAS_OFF);
    float* Wfs  = (float*)(smem + WFS_OFF);
    for (int i = tid; i < 768; i += THREADS) W0s[i] = W0[i];
    if (tid < 256) {
        b0s[tid] = b0[tid];
        bias[tid] = b1[tid]; bias[256 + tid] = b2[tid];
        bias[512 + tid] = b3[tid]; bias[768 + tid] = b4[tid];
        Wfs[tid] = Wf[tid];
    }
    __syncthreads();

    // ---- first layer (SIMT): sin(30*(x@W0^T+b0)) -> A smem hi/lo ----
    {
        int p = tid & 127;
        int half = tid >> 7;           // two threads per point, 128 n each
        int m = blockIdx.x * M_TILE + p;
        float x0 = xyt[3 * m], x1 = xyt[3 * m + 1], x2 = xyt[3 * m + 2];
        char* arow = smem + (uint32_t)p * A_LDB + (uint32_t)half * 256;
#pragma unroll 4
        for (int q = 0; q < 64; q++) {
            int n = half * 128 + 2 * q;
            float z0 = fmaf(x0, W0s[3*n+0], fmaf(x1, W0s[3*n+1], fmaf(x2, W0s[3*n+2], b0s[n])));
            float z1 = fmaf(x0, W0s[3*n+3], fmaf(x1, W0s[3*n+4], fmaf(x2, W0s[3*n+5], b0s[n+1])));
            uint32_t hw, lw;
            split_pack(__sinf(30.0f * z0), __sinf(30.0f * z1), hw, lw);
            *(uint32_t*)(arow + 4 * q)           = hw;
            *(uint32_t*)(arow + A_PLANE + 4 * q) = lw;
        }
    }
    // (first chunk-iteration __syncthreads gates A visibility)

    // ---- 4 hidden layers ----
#pragma unroll 1
    for (int layer = 0; layer < 4; layer++) {
        float acc[4][8][4];
#pragma unroll
        for (int i = 0; i < 4; i++)
#pragma unroll
            for (int j = 0; j < 8; j++)
#pragma unroll
                for (int e = 0; e < 4; e++) acc[i][j][e] = 0.0f;

#pragma unroll 1
        for (int kc = 0; kc < 8; kc++) {
            int g = layer * 8 + kc;
            if (g == 31) { CP_WAIT(0); } else { CP_WAIT(1); }
            __syncthreads();
            uint32_t wb = sb + WBUF_OFF + (uint32_t)(g & 1) * W_CHUNK;

#pragma unroll
            for (int ks = 0; ks < 2; ks++) {
                int kh = kc * 32 + ks * 16;   // k offset in halves
                // B fragments for this k16: 4 x4-ldsm per plane (2 n8-tiles each)
                uint32_t bh[4][4], bl[4][4];
#pragma unroll
                for (int jj = 0; jj < 4; jj++) {
                    uint32_t baddr = wb
                        + (uint32_t)((warp_n * 64 + jj * 16 + (lane & 7) + ((lane >> 4) * 8)) * W_LDB)
                        + (uint32_t)(ks * 32 + ((lane >> 3) & 1) * 16);
                    LDSM_X4(bh[jj][0], bh[jj][1], bh[jj][2], bh[jj][3], baddr);
                    LDSM_X4(bl[jj][0], bl[jj][1], bl[jj][2], bl[jj][3], baddr + W_PLANE);
                }
#pragma unroll
                for (int i = 0; i < 4; i++) {
                    uint32_t aaddr = sb
                        + (uint32_t)((warp_m * 64 + i * 16 + (lane & 15)) * A_LDB)
                        + (uint32_t)(kh * 2 + (lane >> 4) * 16);
                    uint32_t ah0, ah1, ah2, ah3, al0, al1, al2, al3;
                    LDSM_X4(ah0, ah1, ah2, ah3, aaddr);
                    LDSM_X4(al0, al1, al2, al3, aaddr + A_PLANE);
#pragma unroll
                    for (int j = 0; j < 8; j++) {
                        uint32_t b0h = bh[j >> 1][(j & 1) * 2], b1h = bh[j >> 1][(j & 1) * 2 + 1];
                        uint32_t b0l = bl[j >> 1][(j & 1) * 2], b1l = bl[j >> 1][(j & 1) * 2 + 1];
                        MMA_BF16(acc[i][j], ah0, ah1, ah2, ah3, b0h, b1h);
                        MMA_BF16(acc[i][j], al0, al1, al2, al3, b0h, b1h);
                        MMA_BF16(acc[i][j], ah0, ah1, ah2, ah3, b0l, b1l);
                    }
                }
            }
            __syncthreads();
            if (g + 2 < 32) prefetch_chunk(sb, tid, g + 2);
        }

        // ---- epilogue ----
        if (layer < 3) {
            const float* bs = bias + layer * 256;
#pragma unroll
            for (int i = 0; i < 4; i++) {
                int r0 = warp_m * 64 + i * 16 + (lane >> 2);
#pragma unroll
                for (int j = 0; j < 8; j++) {
                    int n0 = warp_n * 64 + j * 8 + (lane & 3) * 2;
                    uint32_t off = (uint32_t)(r0 * A_LDB + n0 * 2);
                    uint32_t hw, lw;
                    float z0 = acc[i][j][0] + bs[n0];
                    float z1 = acc[i][j][1] + bs[n0 + 1];
                    split_pack(__sinf(z0), __sinf(z1), hw, lw);
                    *(uint32_t*)(smem + off)           = hw;
                    *(uint32_t*)(smem + A_PLANE + off) = lw;
                    z0 = acc[i][j][2] + bs[n0];
                    z1 = acc[i][j][3] + bs[n0 + 1];
                    split_pack(__sinf(z0), __sinf(z1), hw, lw);
                    off += 8u * A_LDB;
                    *(uint32_t*)(smem + off)           = hw;
                    *(uint32_t*)(smem + A_PLANE + off) = lw;
                }
            }
            // next iteration's post-CP_WAIT __syncthreads gates these writes
        } else {
            // final: out[m] = sum_n sin(z[m,n]) * Wf[n] + bf
            const float* bs = bias + 768;
            float* red = (float*)(smem + RED_OFF);
#pragma unroll
            for (int i = 0; i < 4; i++) {
                float p0 = 0.0f, p1 = 0.0f;
#pragma unroll
                for (int j = 0; j < 8; j++) {
                    int n0 = warp_n * 64 + j * 8 + (lane & 3) * 2;
                    p0 = fmaf(__sinf(acc[i][j][0] + bs[n0]),     Wfs[n0],     p0);
                    p0 = fmaf(__sinf(acc[i][j][1] + bs[n0 + 1]), Wfs[n0 + 1], p0);
                    p1 = fmaf(__sinf(acc[i][j][2] + bs[n0]),     Wfs[n0],     p1);
                    p1 = fmaf(__sinf(acc[i][j][3] + bs[n0 + 1]), Wfs[n0 + 1], p1);
                }
                p0 += __shfl_xor_sync(0xffffffffu, p0, 1);
                p0 += __shfl_xor_sync(0xffffffffu, p0, 2);
                p1 += __shfl_xor_sync(0xffffffffu, p1, 1);
                p1 += __shfl_xor_sync(0xffffffffu, p1, 2);
                if ((lane & 3) == 0) {
                    int r0 = warp_m * 64 + i * 16 + (lane >> 2);
                    red[r0 * 4 + warp_n]       = p0;
                    red[(r0 + 8) * 4 + warp_n] = p1;
                }
            }
            __syncthreads();
            if (tid < 128) {
                float s = red[tid * 4] + red[tid * 4 + 1] +
                          red[tid * 4 + 2] + red[tid * 4 + 3] + bfp[0];
                out[(size_t)blockIdx.x * M_TILE + tid] = s;
            }
        }
    }
}

// ---------------------------------------------------------------------------
// kernel_launch
// ---------------------------------------------------------------------------
extern "C" void kernel_launch(void* const* d_in, const int* in_sizes, int n_in,
                              void* d_out, int out_size) {
    const float* xyt = (const float*)d_in[0];
    const float* W0  = (const float*)d_in[1];
    const float* b0  = (const float*)d_in[2];
    const float* W1  = (const float*)d_in[3];
    const float* b1  = (const float*)d_in[4];
    const float* W2  = (const float*)d_in[5];
    const float* b2  = (const float*)d_in[6];
    const float* W3  = (const float*)d_in[7];
    const float* b3  = (const float*)d_in[8];
    const float* W4  = (const float*)d_in[9];
    const float* b4  = (const float*)d_in[10];
    const float* Wf  = (const float*)d_in[11];
    const float* bf  = (const float*)d_in[12];
    float* out = (float*)d_out;
    (void)in_sizes; (void)n_in; (void)out_size;

    cudaFuncSetAttribute(siren_mma_kernel,
                         cudaFuncAttributeMaxDynamicSharedMemorySize, SMEM_TOTAL);

    prep_weights<<<512, 256>>>(W1, W2, W3, W4);
    siren_mma_kernel<<<GRID_CTAS, THREADS, SMEM_TOTAL>>>(
        xyt, W0, b0, b1, b2, b3, b4, Wf, bf, out);
}